// round 13
// baseline (speedup 1.0000x reference)
#include <cuda_runtime.h>
#include <cuda_fp16.h>
#include <cstdint>

// Shapes (fixed)
#define NB 4
#define NQ 512
#define NK 512
#define ND 256
#define NH 256

__device__ float  g_qh[NB * NQ * NH];    // projected queries, f32, row-major
__device__ __half g_khT[NB * NH * NK];   // projected keys, f16, TRANSPOSED [b][h][key]
__device__ __half g_vh[NB * NK * ND];    // values, f16

__device__ __forceinline__ unsigned hadd2_u(unsigned a, unsigned b) {
    unsigned r; asm("add.rn.f16x2 %0, %1, %2;" : "=r"(r) : "r"(a), "r"(b)); return r;
}
__device__ __forceinline__ unsigned tanh2_u(unsigned x) {
    unsigned r; asm("tanh.approx.f16x2 %0, %1;" : "=r"(r) : "r"(x)); return r;
}
__device__ __forceinline__ unsigned hfma2_u(unsigned a, unsigned b, unsigned c) {
    unsigned r; asm("fma.rn.f16x2 %0, %1, %2, %3;" : "=r"(r) : "r"(a), "r"(b), "r"(c)); return r;
}
__device__ __forceinline__ float2 h2f2(unsigned h) {
    __half2 hh = *reinterpret_cast<__half2*>(&h);
    return __half22float2(hh);
}
__device__ __forceinline__ unsigned f2h2(float lo, float hi) {
    __half2 hh = __floats2half2_rn(lo, hi);
    return *reinterpret_cast<unsigned*>(&hh);
}

// ---------------------------------------------------------------------------
// Projection GEMM: C[2048x256] = A[2048x256] @ W[256x256]
// z = 0 -> g_qh (f32, row-major); z = 1 -> g_khT (f16, TRANSPOSED via smem)
// ---------------------------------------------------------------------------
__global__ __launch_bounds__(256) void proj_kernel(
    const float* __restrict__ Aq, const float* __restrict__ Wq,
    const float* __restrict__ Ak, const float* __restrict__ Wk)
{
    const float* A; const float* W;
    if (blockIdx.z == 0) { A = Aq; W = Wq; }
    else                 { A = Ak; W = Wk; }

    __shared__ float sraw[2 * 16 * 68];            // As | Bs; reused for transpose
    float* As = sraw;                              // [16][68]
    float* Bs = sraw + 16 * 68;                    // [16][68]

    const int t    = threadIdx.x;
    const int row0 = blockIdx.y * 64;
    const int col0 = blockIdx.x * 64;
    const int ty   = t >> 4;
    const int tx   = t & 15;

    float acc[4][4] = {};

    for (int k0 = 0; k0 < ND; k0 += 16) {
        {
            int r  = t >> 2;
            int c4 = (t & 3) * 4;
            float4 v = *(const float4*)&A[(row0 + r) * ND + k0 + c4];
            As[(c4 + 0) * 68 + r] = v.x;
            As[(c4 + 1) * 68 + r] = v.y;
            As[(c4 + 2) * 68 + r] = v.z;
            As[(c4 + 3) * 68 + r] = v.w;
        }
        {
            int r  = t >> 4;
            int c4 = (t & 15) * 4;
            *(float4*)&Bs[r * 68 + c4] = *(const float4*)&W[(k0 + r) * NH + col0 + c4];
        }
        __syncthreads();
        #pragma unroll
        for (int kk = 0; kk < 16; kk++) {
            float4 av = *(float4*)&As[kk * 68 + ty * 4];
            float4 bv = *(float4*)&Bs[kk * 68 + tx * 4];
            float a_[4] = {av.x, av.y, av.z, av.w};
            float b_[4] = {bv.x, bv.y, bv.z, bv.w};
            #pragma unroll
            for (int i = 0; i < 4; i++)
                #pragma unroll
                for (int j = 0; j < 4; j++)
                    acc[i][j] += a_[i] * b_[j];
        }
        __syncthreads();
    }

    if (blockIdx.z == 0) {
        #pragma unroll
        for (int i = 0; i < 4; i++) {
            float4 v = make_float4(acc[i][0], acc[i][1], acc[i][2], acc[i][3]);
            *(float4*)&g_qh[(row0 + ty * 4 + i) * NH + col0 + tx * 4] = v;
        }
    } else {
        // transpose 64x64 tile through smem, emit f16 to g_khT[b][h][key]
        __half* ts = (__half*)sraw;                // 64 x 68 halfs = 8704 B (fits)
        #pragma unroll
        for (int i = 0; i < 4; i++) {
            uint2 u;
            u.x = f2h2(acc[i][0], acc[i][1]);
            u.y = f2h2(acc[i][2], acc[i][3]);
            *(uint2*)&ts[(ty * 4 + i) * 68 + tx * 4] = u;   // ts[key][h]
        }
        __syncthreads();

        const int h  = t & 63;
        const int kg = t >> 6;                     // 4 groups of 16 keys
        const int b2     = row0 >> 9;              // batch (keys 512-aligned per batch)
        const int rowInB = row0 & 511;

        uint4 pk[2];
        __half* tmp = (__half*)pk;
        #pragma unroll
        for (int kk = 0; kk < 16; kk++)
            tmp[kk] = ts[(kg * 16 + kk) * 68 + h];

        __half* dst = &g_khT[((size_t)(b2 * NH + col0 + h)) * NK + rowInB + kg * 16];
        *(uint4*)dst       = pk[0];
        *(uint4*)(dst + 8) = pk[1];
    }
}

// ---------------------------------------------------------------------------
// values f32 -> f16 (one-time): 512 blocks x 256 threads, 1 float4 each.
// ---------------------------------------------------------------------------
__global__ __launch_bounds__(256) void convert_v_kernel(const float* __restrict__ values)
{
    int i = blockIdx.x * 256 + threadIdx.x;         // 0 .. 131071 float4s
    float4 v = *(const float4*)&values[(size_t)i * 4];
    uint2 u;
    u.x = f2h2(v.x, v.y);
    u.y = f2h2(v.z, v.w);
    *(uint2*)&g_vh[(size_t)i * 4] = u;
}

// ---------------------------------------------------------------------------
// Fused attention, BARRIER-FREE: warps are independent L2-streaming consumers.
//  - Phase A: lane = key-pair of 64-key group g; per h-step:
//      LDG.32 kv (g_khT, L2/L1), LDS.64 {q2,wv2} broadcast (warp-private smem),
//      HADD2 + TANH2 + HFMA2. Scores in registers; no shuffle reduction.
//  - Phase B: register softmax + warp shuffles; unnormalized e -> attn_s row.
//  - Phase C: f16 values; per key one LDG.128 covers the 256-d row;
//      register f32 accumulation. No __syncthreads anywhere.
// 512 blocks x 128 threads = 4 warps = 4 queries of batch (blockIdx & 3).
// ---------------------------------------------------------------------------
__global__ __launch_bounds__(128) void attn_kernel(
    const float* __restrict__ wv,
    const int*   __restrict__ valid_lens,
    float*       __restrict__ out)
{
    __shared__ uint2 s_qw[4][256];     // per-warp {q2dup, wv2dup}  (8 KB)
    __shared__ float attn_s[4][512];   // per-warp unnormalized exp (8 KB)

    const int t    = threadIdx.x;
    const int w    = t >> 5;                       // warp = query
    const int lane = t & 31;
    const int b    = blockIdx.x & 3;               // batch-interleaved
    const int qblk = blockIdx.x >> 2;              // 0..127
    const int vl   = valid_lens[b];                // uniform across block
    const int qrow = b * NQ + qblk * 4 + w;

    // ---------------- prologue: per-warp q2/wv2 into warp-private smem ------
    {
        const float* qp = &g_qh[(size_t)qrow * NH];
        #pragma unroll
        for (int i = 0; i < 8; i++) {
            int h = lane + 32 * i;
            float qv  = qp[h];
            float wvv = wv[h];
            uint2 e;
            e.x = f2h2(qv, qv);
            e.y = f2h2(wvv, wvv);
            s_qw[w][h] = e;
        }
    }
    __syncwarp();

    // ---------------- Phase A: scores -> registers ----------------
    const unsigned* kp = (const unsigned*)&g_khT[(size_t)b * NH * NK];  // [256][256] f16x2
    float sc0[8], sc1[8];

    #pragma unroll
    for (int g = 0; g < 8; ++g) {
        if (g * 64 < vl) {
            float s0 = 0.f, s1 = 0.f;
            const unsigned* kg = kp + g * 32 + lane;
            for (int h0 = 0; h0 < 256; h0 += 16) {
                unsigned acc0 = 0u, acc1 = 0u, acc2 = 0u, acc3 = 0u;
                const unsigned* kh0 = kg + h0 * (NK / 2);
                #pragma unroll
                for (int hw = 0; hw < 16; hw += 4) {
                    unsigned kva = kh0[(hw + 0) * (NK / 2)];
                    unsigned kvb = kh0[(hw + 1) * (NK / 2)];
                    unsigned kvc = kh0[(hw + 2) * (NK / 2)];
                    unsigned kvd = kh0[(hw + 3) * (NK / 2)];
                    uint2 qa = s_qw[w][h0 + hw + 0];
                    uint2 qb = s_qw[w][h0 + hw + 1];
                    uint2 qc = s_qw[w][h0 + hw + 2];
                    uint2 qd = s_qw[w][h0 + hw + 3];
                    acc0 = hfma2_u(qa.y, tanh2_u(hadd2_u(kva, qa.x)), acc0);
                    acc1 = hfma2_u(qb.y, tanh2_u(hadd2_u(kvb, qb.x)), acc1);
                    acc2 = hfma2_u(qc.y, tanh2_u(hadd2_u(kvc, qc.x)), acc2);
                    acc3 = hfma2_u(qd.y, tanh2_u(hadd2_u(kvd, qd.x)), acc3);
                }
                float2 f0 = h2f2(acc0), f1 = h2f2(acc1);
                float2 f2v = h2f2(acc2), f3 = h2f2(acc3);
                s0 += (f0.x + f1.x) + (f2v.x + f3.x);
                s1 += (f0.y + f1.y) + (f2v.y + f3.y);
            }
            sc0[g] = s0;
            sc1[g] = s1;
        } else {
            sc0[g] = -1.0e6f;
            sc1[g] = -1.0e6f;
        }
    }

    // mask tail
    #pragma unroll
    for (int g = 0; g < 8; ++g) {
        int k = g * 64 + 2 * lane;
        if (k     >= vl) sc0[g] = -1.0e6f;
        if (k + 1 >= vl) sc1[g] = -1.0e6f;
    }

    // ---------------- Phase B: softmax (registers + shuffles) ----------------
    float mx = -1.0e30f;
    #pragma unroll
    for (int g = 0; g < 8; ++g) {
        mx = fmaxf(mx, sc0[g]);
        mx = fmaxf(mx, sc1[g]);
    }
    #pragma unroll
    for (int o = 16; o > 0; o >>= 1)
        mx = fmaxf(mx, __shfl_xor_sync(0xffffffffu, mx, o));

    float sum = 0.f;
    #pragma unroll
    for (int g = 0; g < 8; ++g) {
        float e0 = __expf(sc0[g] - mx);            // masked -> exact 0
        float e1 = __expf(sc1[g] - mx);
        sum += e0 + e1;
        attn_s[w][g * 64 + 2 * lane]     = e0;
        attn_s[w][g * 64 + 2 * lane + 1] = e1;
    }
    #pragma unroll
    for (int o = 16; o > 0; o >>= 1)
        sum += __shfl_xor_sync(0xffffffffu, sum, o);
    const float inv = 1.0f / sum;
    __syncwarp();                                  // attn_s row visible within warp

    // ---------------- Phase C: out = attn @ values (f16 values, reg accum) --
    const uint4* vbh = (const uint4*)&g_vh[(size_t)(b * NK) * ND];  // row = 32 uint4
    float o0 = 0.f, o1 = 0.f, o2 = 0.f, o3 = 0.f;
    float o4 = 0.f, o5 = 0.f, o6 = 0.f, o7 = 0.f;
    const int vl4 = (vl + 3) & ~3;

    for (int k0 = 0; k0 < vl4; k0 += 4) {
        #pragma unroll
        for (int j = 0; j < 4; ++j) {
            float a  = attn_s[w][k0 + j];                  // LDS broadcast
            uint4 vv = vbh[(k0 + j) * 32 + lane];          // 8 halfs: d = lane*8..+8
            float2 f0 = h2f2(vv.x);
            float2 f1 = h2f2(vv.y);
            float2 f2v = h2f2(vv.z);
            float2 f3 = h2f2(vv.w);
            o0 += a * f0.x;  o1 += a * f0.y;
            o2 += a * f1.x;  o3 += a * f1.y;
            o4 += a * f2v.x; o5 += a * f2v.y;
            o6 += a * f3.x;  o7 += a * f3.y;
        }
    }

    float4 r0 = make_float4(o0 * inv, o1 * inv, o2 * inv, o3 * inv);
    float4 r1 = make_float4(o4 * inv, o5 * inv, o6 * inv, o7 * inv);
    *(float4*)&out[(size_t)qrow * ND + lane * 8]     = r0;
    *(float4*)&out[(size_t)qrow * ND + lane * 8 + 4] = r1;
}

// ---------------------------------------------------------------------------
extern "C" void kernel_launch(void* const* d_in, const int* in_sizes, int n_in,
                              void* d_out, int out_size)
{
    const float* queries = (const float*)d_in[0];
    const float* keys    = (const float*)d_in[1];
    const float* values  = (const float*)d_in[2];
    const float* Wq      = (const float*)d_in[3];
    const float* Wk      = (const float*)d_in[4];
    const float* wv      = (const float*)d_in[5];
    const int*   vlen    = (const int*)d_in[6];
    float* out = (float*)d_out;

    (void)in_sizes; (void)n_in; (void)out_size;

    dim3 pgrid(NH / 64, (NB * NQ) / 64, 2);
    proj_kernel<<<pgrid, 256>>>(queries, Wq, keys, Wk);
    convert_v_kernel<<<(NB * NK * ND) / 4 / 256, 256>>>(values);

    attn_kernel<<<(NB * NQ) / 4, 128>>>(wv, vlen, out);
}

// round 14
// speedup vs baseline: 1.3770x; 1.3770x over previous
#include <cuda_runtime.h>
#include <cuda_bf16.h>

// Shapes (fixed for this problem)
#define NB 4
#define NQ 512
#define NK 512
#define ND 256
#define NH 256

#define STRIDE 260            // smem row stride (floats): 16B-aligned, bank-friendly

// Scratch: projected queries/keys (B*Q x H) and (B*K x H)
__device__ float g_qh[NB * NQ * NH];
__device__ float g_kh[NB * NK * NH];

__device__ __forceinline__ float tanh_ap(float x) {
    float y;
    asm("tanh.approx.f32 %0, %1;" : "=f"(y) : "f"(x));
    return y;
}

// ---------------------------------------------------------------------------
// Projection GEMM: C[2048x256] = A[2048x256] @ W[256x256]
// blockIdx.z = 0 -> (queries, Wq, g_qh), 1 -> (keys, Wk, g_kh)
// 64x64 output tile per block, BK=16, 256 threads, 4x4 micro-tile.
// ---------------------------------------------------------------------------
__global__ __launch_bounds__(256) void proj_kernel(
    const float* __restrict__ Aq, const float* __restrict__ Wq,
    const float* __restrict__ Ak, const float* __restrict__ Wk)
{
    const float* A; const float* W; float* C;
    if (blockIdx.z == 0) { A = Aq; W = Wq; C = g_qh; }
    else                 { A = Ak; W = Wk; C = g_kh; }

    __shared__ float As[16][68];   // [k][m], transposed on store
    __shared__ float Bs[16][68];   // [k][n]

    const int t    = threadIdx.x;
    const int row0 = blockIdx.y * 64;
    const int col0 = blockIdx.x * 64;
    const int ty   = t >> 4;
    const int tx   = t & 15;

    float acc[4][4] = {};

    for (int k0 = 0; k0 < ND; k0 += 16) {
        // A tile: 64 rows x 16 cols, transpose into As[k][m]
        {
            int r  = t >> 2;           // 0..63
            int c4 = (t & 3) * 4;      // 0,4,8,12
            float4 v = *(const float4*)&A[(row0 + r) * ND + k0 + c4];
            As[c4 + 0][r] = v.x;
            As[c4 + 1][r] = v.y;
            As[c4 + 2][r] = v.z;
            As[c4 + 3][r] = v.w;
        }
        // W tile: 16 rows x 64 cols
        {
            int r  = t >> 4;           // 0..15
            int c4 = (t & 15) * 4;     // 0..60
            *(float4*)&Bs[r][c4] = *(const float4*)&W[(k0 + r) * NH + col0 + c4];
        }
        __syncthreads();
        #pragma unroll
        for (int kk = 0; kk < 16; kk++) {
            float4 av = *(float4*)&As[kk][ty * 4];   // broadcast within half-warp
            float4 bv = *(float4*)&Bs[kk][tx * 4];
            float a_[4] = {av.x, av.y, av.z, av.w};
            float b_[4] = {bv.x, bv.y, bv.z, bv.w};
            #pragma unroll
            for (int i = 0; i < 4; i++)
                #pragma unroll
                for (int j = 0; j < 4; j++)
                    acc[i][j] += a_[i] * b_[j];
        }
        __syncthreads();
    }

    #pragma unroll
    for (int i = 0; i < 4; i++) {
        float4 v = make_float4(acc[i][0], acc[i][1], acc[i][2], acc[i][3]);
        *(float4*)&C[(row0 + ty * 4 + i) * NH + col0 + tx * 4] = v;
    }
}

// ---------------------------------------------------------------------------
// Fused scores (tanh additive) + masked softmax + attn @ values.
// EXACT R1 structure (best measured: attn 88.2us); ONLY change: batch-
// interleaved block mapping (b = blockIdx & 3) so every wave mixes all four
// valid_lens values instead of grouping 64 consecutive blocks per batch.
// Block = 256 threads = 8 warps = 8 queries of one batch.
// ---------------------------------------------------------------------------
__global__ __launch_bounds__(256, 2) void attn_kernel(
    const float* __restrict__ values,
    const float* __restrict__ wv,
    const int*   __restrict__ valid_lens,
    float*       __restrict__ out)
{
    __shared__ float sbuf[32 * STRIDE];    // 33280 B: kh tiles (A) / values tiles + attn (C)
    __shared__ float s_qh[8 * NH];         // 8192 B
    __shared__ float s_wv[NH];             // 1024 B
    float* attn_s = &sbuf[16 * STRIDE];    // 8*512 floats, disjoint from 16-key values tile

    const int t    = threadIdx.x;
    const int w    = t >> 5;
    const int lane = t & 31;
    const int b    = blockIdx.x & 3;               // batch-interleaved (ONLY change vs R1)
    const int qblk = blockIdx.x >> 2;              // 0..63
    const int qrow = b * NQ + qblk * 8 + w;        // global row in [0, B*Q)
    const int vl   = valid_lens[b];                // uniform across block

    // Stage qh rows for this block's 8 queries + wv
    #pragma unroll
    for (int rr = 0; rr < 2; rr++) {
        int i = t + 256 * rr;                      // 0..511 float4 slots
        int r = i >> 6;
        int c = (i & 63) * 4;
        *(float4*)&s_qh[r * NH + c] =
            *(const float4*)&g_qh[(b * NQ + qblk * 8 + r) * NH + c];
    }
    if (t < 64) *(float4*)&s_wv[t * 4] = *(const float4*)&wv[t * 4];
    __syncthreads();

    // ---------------- Phase A: scores ----------------
    float sc[16];
    #pragma unroll
    for (int i = 0; i < 16; i++) sc[i] = -1.0e6f;

    const float* khb = &g_kh[(b * NK) * NH];
    const float* myq = &s_qh[w * NH];

    #pragma unroll
    for (int tile = 0; tile < 16; ++tile) {
        if (tile * 32 < vl) {                      // uniform branch (vl per-block)
            // load kh tile: 32 keys x 256 h  (2048 float4, 8 per thread)
            #pragma unroll
            for (int r = 0; r < 8; ++r) {
                int i  = t + 256 * r;
                int k  = i >> 6;
                int h4 = (i & 63) * 4;
                *(float4*)&sbuf[k * STRIDE + h4] =
                    *(const float4*)&khb[(tile * 32 + k) * NH + h4];
            }
            __syncthreads();

            float acc = 0.f;
            const float* myk = &sbuf[lane * STRIDE];
            #pragma unroll 4
            for (int h = 0; h < NH; h += 4) {
                float4 kv  = *(const float4*)&myk[h];
                float4 qv  = *(const float4*)&myq[h];    // broadcast
                float4 wv4 = *(const float4*)&s_wv[h];   // broadcast
                acc += wv4.x * tanh_ap(qv.x + kv.x);
                acc += wv4.y * tanh_ap(qv.y + kv.y);
                acc += wv4.z * tanh_ap(qv.z + kv.z);
                acc += wv4.w * tanh_ap(qv.w + kv.w);
            }
            sc[tile] = acc;                        // key = tile*32 + lane
            __syncthreads();
        }
    }

    // mask tail keys of the partial tile
    #pragma unroll
    for (int i = 0; i < 16; i++) {
        int k = i * 32 + lane;
        if (k >= vl) sc[i] = -1.0e6f;
    }

    __syncthreads();   // everyone done reading sbuf before attn_s writes overlay it

    // ---------------- Phase B: softmax (registers + shuffles) ----------------
    float mx = -1.0e30f;
    #pragma unroll
    for (int i = 0; i < 16; i++) mx = fmaxf(mx, sc[i]);
    #pragma unroll
    for (int o = 16; o > 0; o >>= 1)
        mx = fmaxf(mx, __shfl_xor_sync(0xffffffffu, mx, o));

    float sum = 0.f;
    #pragma unroll
    for (int i = 0; i < 16; i++) {
        float e = __expf(sc[i] - mx);              // masked -> exact 0 (underflow)
        sum += e;
        attn_s[w * NK + i * 32 + lane] = e;        // unnormalized
    }
    #pragma unroll
    for (int o = 16; o > 0; o >>= 1)
        sum += __shfl_xor_sync(0xffffffffu, sum, o);
    const float inv = 1.0f / sum;

    // ---------------- Phase C: out = attn @ values ----------------
    float4 o0 = make_float4(0.f, 0.f, 0.f, 0.f);
    float4 o1 = make_float4(0.f, 0.f, 0.f, 0.f);
    const int nTilesC = (vl + 15) >> 4;
    const float* vb = &values[(b * NK) * ND];

    for (int tile = 0; tile < nTilesC; ++tile) {
        __syncthreads();                           // tile t reads done / attn_s ready
        // load values tile: 16 keys x 256 d (1024 float4, 4 per thread)
        #pragma unroll
        for (int r = 0; r < 4; ++r) {
            int i  = t + 256 * r;
            int k  = i >> 6;
            int h4 = (i & 63) * 4;
            *(float4*)&sbuf[k * STRIDE + h4] =
                *(const float4*)&vb[(tile * 16 + k) * ND + h4];
        }
        __syncthreads();

        #pragma unroll 4
        for (int kk = 0; kk < 16; ++kk) {
            float a = attn_s[w * NK + tile * 16 + kk];        // broadcast
            float4 v0 = *(const float4*)&sbuf[kk * STRIDE + 4 * lane];
            float4 v1 = *(const float4*)&sbuf[kk * STRIDE + 128 + 4 * lane];
            o0.x += a * v0.x; o0.y += a * v0.y; o0.z += a * v0.z; o0.w += a * v0.w;
            o1.x += a * v1.x; o1.y += a * v1.y; o1.z += a * v1.z; o1.w += a * v1.w;
        }
    }

    o0.x *= inv; o0.y *= inv; o0.z *= inv; o0.w *= inv;
    o1.x *= inv; o1.y *= inv; o1.z *= inv; o1.w *= inv;
    *(float4*)&out[qrow * ND + 4 * lane]       = o0;
    *(float4*)&out[qrow * ND + 128 + 4 * lane] = o1;
}

// ---------------------------------------------------------------------------
extern "C" void kernel_launch(void* const* d_in, const int* in_sizes, int n_in,
                              void* d_out, int out_size)
{
    const float* queries = (const float*)d_in[0];  // (B,Q,D)
    const float* keys    = (const float*)d_in[1];  // (B,K,D)
    const float* values  = (const float*)d_in[2];  // (B,K,D)
    const float* Wq      = (const float*)d_in[3];  // (D,H)
    const float* Wk      = (const float*)d_in[4];  // (D,H)
    const float* wv      = (const float*)d_in[5];  // (H,)
    const int*   vlen    = (const int*)d_in[6];    // (B,) int32
    float* out = (float*)d_out;                    // (B,Q,D)

    (void)in_sizes; (void)n_in; (void)out_size;

    dim3 pgrid(NH / 64, (NB * NQ) / 64, 2);        // 4 x 32 x 2
    proj_kernel<<<pgrid, 256>>>(queries, Wq, keys, Wk);

    attn_kernel<<<(NB * NQ) / 8, 256>>>(values, wv, vlen, out);
}